// round 8
// baseline (speedup 1.0000x reference)
#include <cuda_runtime.h>

#define NROWS 65536   // N_TOKENS * BATCH
#define FDIM  256     // HW
#define MDIM  1024    // MEM_DIM

// ---------------- scratch (static device globals; no allocation) ----------------
__device__ float g_q[NROWS * FDIM];             // raw q, row-major [N, F]        (64 MB)
__device__ float g_qm[NROWS];
__device__ float g_qv[NROWS];
__device__ float g_kcT[FDIM * MDIM];            // centered k, TRANSPOSED [F, M]  (1 MB)
__device__ float g_vmat[MDIM * FDIM];           // v, row-major [M, F]            (1 MB)
__device__ float g_km[MDIM];
__device__ float g_kv[MDIM];
__device__ float g_S[(size_t)NROWS * MDIM];     // p = exp(ssim) [N, M]           (256 MB)
__device__ float g_psum[8 * NROWS];             // per-m-block partial row sums   (2 MB)

// ---------------- packed f32x2 helpers (full-rate FP32 on sm_103a) --------------
__device__ __forceinline__ unsigned long long pk2(float lo, float hi) {
    unsigned long long r;
    asm("mov.b64 %0, {%1, %2};" : "=l"(r) : "f"(lo), "f"(hi));
    return r;
}
__device__ __forceinline__ void fma2(unsigned long long& d, unsigned long long a,
                                     unsigned long long b) {
    asm("fma.rn.f32x2 %0, %1, %2, %0;" : "+l"(d) : "l"(a), "l"(b));
}
__device__ __forceinline__ float2 upk2(unsigned long long v) {
    float2 r;
    asm("mov.b64 {%0, %1}, %2;" : "=f"(r.x), "=f"(r.y) : "l"(v));
    return r;
}

// ---------------- cp.async helpers ----------------------------------------------
__device__ __forceinline__ void cpa16(void* dst, const void* src) {
    unsigned saddr = (unsigned)__cvta_generic_to_shared(dst);
    asm volatile("cp.async.cg.shared.global [%0], [%1], 16;" ::"r"(saddr), "l"(src));
}
__device__ __forceinline__ void cpa_commit() {
    asm volatile("cp.async.commit_group;" ::: "memory");
}
__device__ __forceinline__ void cpa_wait_all() {
    asm volatile("cp.async.wait_group 0;" ::: "memory");
}

// =================================================================================
// rowgemm: C[64 x 256] = A_tile @ W^T   (W is [256,256] row-major)
// MODE 0: q  -> row stats (mean/var), RAW rows to g_q, g_qm/g_qv
// MODE 1: k  -> row stats, centered TRANSPOSED to g_kcT, g_km/g_kv
// MODE 2: v  -> plain row-major store to g_vmat
// =================================================================================
template <int MODE>
__global__ __launch_bounds__(256, 2) void rowgemm_kernel(const float* __restrict__ A,
                                                         const float* __restrict__ W) {
    __shared__ float As[16][68];    // As[kk][row]
    __shared__ float Bs[16][260];   // Bs[kk][col]

    const int tid = threadIdx.x;
    const int n0  = blockIdx.x * 64;
    const int tr  = tid >> 5;   // 0..7
    const int tc  = tid & 31;   // 0..31

    unsigned long long accp[8][4];
#pragma unroll
    for (int i = 0; i < 8; i++)
#pragma unroll
        for (int j = 0; j < 4; j++) accp[i][j] = 0ull;

    for (int k0 = 0; k0 < 256; k0 += 16) {
        {   // A tile 64x16 (transpose into smem)
            int r = tid >> 2;
            int c = (tid & 3) << 2;
            float4 v = *(const float4*)&A[(n0 + r) * 256 + k0 + c];
            As[c + 0][r] = v.x; As[c + 1][r] = v.y; As[c + 2][r] = v.z; As[c + 3][r] = v.w;
        }
#pragma unroll
        for (int it = 0; it < 4; it++) {   // W tile 256x16 (transpose into smem)
            int fid = tid + (it << 8);
            int j = fid >> 2;
            int c = (fid & 3) << 2;
            float4 v = *(const float4*)&W[j * 256 + k0 + c];
            Bs[c + 0][j] = v.x; Bs[c + 1][j] = v.y; Bs[c + 2][j] = v.z; Bs[c + 3][j] = v.w;
        }
        __syncthreads();
#pragma unroll
        for (int kk = 0; kk < 16; kk++) {
            float4 a0 = *(const float4*)&As[kk][tr * 4];
            float4 a1 = *(const float4*)&As[kk][32 + tr * 4];
            ulonglong2 b0 = *(const ulonglong2*)(const void*)&Bs[kk][tc * 4];
            ulonglong2 b1 = *(const ulonglong2*)(const void*)&Bs[kk][128 + tc * 4];
            unsigned long long ap[8] = {pk2(a0.x, a0.x), pk2(a0.y, a0.y), pk2(a0.z, a0.z),
                                        pk2(a0.w, a0.w), pk2(a1.x, a1.x), pk2(a1.y, a1.y),
                                        pk2(a1.z, a1.z), pk2(a1.w, a1.w)};
            unsigned long long bv[4] = {b0.x, b0.y, b1.x, b1.y};
#pragma unroll
            for (int i = 0; i < 8; i++)
#pragma unroll
                for (int j = 0; j < 4; j++) fma2(accp[i][j], ap[i], bv[j]);
        }
        __syncthreads();
    }

    float acc[8][8];
#pragma unroll
    for (int i = 0; i < 8; i++)
#pragma unroll
        for (int j2 = 0; j2 < 4; j2++) {
            float2 u = upk2(accp[i][j2]);
            acc[i][2 * j2 + 0] = u.x;
            acc[i][2 * j2 + 1] = u.y;
        }

#pragma unroll
    for (int i = 0; i < 8; i++) {
        const int row = n0 + tr * 4 + (i & 3) + ((i >> 2) << 5);
        if (MODE == 2) {
            *(float4*)&g_vmat[row * 256 + tc * 4] =
                make_float4(acc[i][0], acc[i][1], acc[i][2], acc[i][3]);
            *(float4*)&g_vmat[row * 256 + 128 + tc * 4] =
                make_float4(acc[i][4], acc[i][5], acc[i][6], acc[i][7]);
        } else {
            float s = 0.f, ss = 0.f;
#pragma unroll
            for (int j = 0; j < 8; j++) { s += acc[i][j]; ss += acc[i][j] * acc[i][j]; }
#pragma unroll
            for (int o = 16; o > 0; o >>= 1) {
                s  += __shfl_xor_sync(0xffffffffu, s, o);
                ss += __shfl_xor_sync(0xffffffffu, ss, o);
            }
            const float mean = s * (1.0f / 256.0f);
            const float var  = (ss - 256.0f * mean * mean) * (1.0f / 255.0f);
            if (MODE == 0) {
                if (tc == 0) { g_qm[row] = mean; g_qv[row] = var; }
                // store RAW q: cov = q . kcT is exact since sum(kcT col) == 0
                *(float4*)&g_q[row * 256 + tc * 4] =
                    make_float4(acc[i][0], acc[i][1], acc[i][2], acc[i][3]);
                *(float4*)&g_q[row * 256 + 128 + tc * 4] =
                    make_float4(acc[i][4], acc[i][5], acc[i][6], acc[i][7]);
            } else {   // MODE 1: k -> centered transposed
                if (tc == 0) { g_km[row] = mean; g_kv[row] = var; }
#pragma unroll
                for (int j = 0; j < 8; j++) {
                    const int col = tc * 4 + (j & 3) + ((j >> 2) << 7);
                    g_kcT[col * 1024 + row] = acc[i][j] - mean;
                }
            }
        }
    }
}

// =================================================================================
// 128x128x(BK=32) tile engine, single-sync pipeline:
//   A: LDG -> regs (issued before mma of prev tile) -> duplicated STS after mma
//      smem layout As2[kk][2*row(+dup)] so the broadcast f32x2 pair is ONE LDS.128
//   B: cp.async verbatim copy, waited at next iteration top
// Thread (tr=tid>>4, tc=tid&15): rows tr*4+i (+64), cols tc*4+j (+64).
// =================================================================================
#define A_STR 268                     // 2*128 + 12 pad (16B aligned, breaks STS banks)
#define B_STR 132
#define A_BUF (32 * A_STR)            // 8576 floats
#define B_BUF (32 * B_STR)            // 4224 floats
#define SMEM_BYTES ((2 * A_BUF + 2 * B_BUF) * 4)   // 102400

__device__ __forceinline__ void lda_regs(float4 av[4], const float* __restrict__ Agl,
                                         int a_ld, int tid) {
#pragma unroll
    for (int it = 0; it < 4; it++) {   // A tile: 128 rows x 32 floats, coalesced
        int ch = tid + (it << 8);
        int r = ch >> 3, c = (ch & 7) << 2;
        av[it] = *(const float4*)&Agl[(size_t)r * a_ld + c];
    }
}
__device__ __forceinline__ void sta_dup(const float4 av[4], float* As2, int tid) {
#pragma unroll
    for (int it = 0; it < 4; it++) {
        int ch = tid + (it << 8);
        int r = ch >> 3, c = (ch & 7) << 2;
        *(float2*)&As2[(c + 0) * A_STR + 2 * r] = make_float2(av[it].x, av[it].x);
        *(float2*)&As2[(c + 1) * A_STR + 2 * r] = make_float2(av[it].y, av[it].y);
        *(float2*)&As2[(c + 2) * A_STR + 2 * r] = make_float2(av[it].z, av[it].z);
        *(float2*)&As2[(c + 3) * A_STR + 2 * r] = make_float2(av[it].w, av[it].w);
    }
}
__device__ __forceinline__ void ldb_async(float* Bs, const float* __restrict__ Bgl,
                                          int b_ld, int tid) {
#pragma unroll
    for (int it = 0; it < 4; it++) {   // B tile: 32 rows x 128 floats, verbatim
        int ch = tid + (it << 8);
        int rr = ch >> 5, cc = (ch & 31) << 2;
        cpa16(&Bs[rr * B_STR + cc], &Bgl[(size_t)rr * b_ld + cc]);
    }
    cpa_commit();
}

__device__ __forceinline__ void tile_mma(const float* __restrict__ As2,
                                         const float* __restrict__ Bs, int tr, int tc,
                                         unsigned long long accp[8][4]) {
#pragma unroll
    for (int kk = 0; kk < 32; kk++) {
        const float* a = As2 + kk * A_STR + 8 * tr;
        ulonglong2 a01 = *(const ulonglong2*)(const void*)(a);
        ulonglong2 a23 = *(const ulonglong2*)(const void*)(a + 4);
        ulonglong2 a45 = *(const ulonglong2*)(const void*)(a + 128);
        ulonglong2 a67 = *(const ulonglong2*)(const void*)(a + 132);
        const float* b = Bs + kk * B_STR + 4 * tc;
        ulonglong2 b0 = *(const ulonglong2*)(const void*)(b);
        ulonglong2 b1 = *(const ulonglong2*)(const void*)(b + 64);
        unsigned long long ap[8] = {a01.x, a01.y, a23.x, a23.y,
                                    a45.x, a45.y, a67.x, a67.y};
        unsigned long long bv[4] = {b0.x, b0.y, b1.x, b1.y};
#pragma unroll
        for (int i = 0; i < 8; i++)
#pragma unroll
            for (int j = 0; j < 4; j++) fma2(accp[i][j], ap[i], bv[j]);
    }
}

// =================================================================================
// ssim: P[N, M] = exp(ssim(q, k));  cov = q @ kcT / 255 (q raw: mean term vanishes)
// also writes deterministic per-m-block row-sum partials to g_psum.
// =================================================================================
__global__ __launch_bounds__(256, 2) void ssim_kernel() {
    extern __shared__ float sm[];
    float* Asm[2] = {sm, sm + A_BUF};
    float* Bsm[2] = {sm + 2 * A_BUF, sm + 2 * A_BUF + B_BUF};

    const int tid = threadIdx.x;
    const int n0 = blockIdx.y << 7;
    const int m0 = blockIdx.x << 7;
    const int tr = tid >> 4;
    const int tc = tid & 15;

    unsigned long long accp[8][4];
#pragma unroll
    for (int i = 0; i < 8; i++)
#pragma unroll
        for (int j = 0; j < 4; j++) accp[i][j] = 0ull;

    float4 av[4];
    lda_regs(av, &g_q[(size_t)n0 * 256], 256, tid);
    ldb_async(Bsm[0], &g_kcT[m0], 1024, tid);
    sta_dup(av, Asm[0], tid);

#pragma unroll 1
    for (int t = 0; t < 8; t++) {
        cpa_wait_all();               // B(t) landed (only group in flight)
        __syncthreads();              // all tiles(t) visible; buf[t^1] free
        if (t + 1 < 8) {
            ldb_async(Bsm[(t + 1) & 1], &g_kcT[(size_t)(t + 1) * 32 * 1024 + m0], 1024,
                      tid);
            lda_regs(av, &g_q[(size_t)n0 * 256 + (t + 1) * 32], 256, tid);
        }
        tile_mma(Asm[t & 1], Bsm[t & 1], tr, tc, accp);
        if (t + 1 < 8) sta_dup(av, Asm[(t + 1) & 1], tid);
    }

    float acc[8][8];
#pragma unroll
    for (int i = 0; i < 8; i++)
#pragma unroll
        for (int j2 = 0; j2 < 4; j2++) {
            float2 u = upk2(accp[i][j2]);
            acc[i][2 * j2 + 0] = u.x;
            acc[i][2 * j2 + 1] = u.y;
        }

    const float C1f = 0.01f, C2f = 0.03f, EPSf = 1e-8f, INV255 = 1.0f / 255.0f;

    float qm[8], qv[8], km[8], kv[8];
#pragma unroll
    for (int i = 0; i < 8; i++) {
        const int row = n0 + tr * 4 + (i & 3) + ((i >> 2) << 6);
        qm[i] = g_qm[row];
        qv[i] = g_qv[row];
    }
#pragma unroll
    for (int j = 0; j < 8; j++) {
        const int col = m0 + tc * 4 + (j & 3) + ((j >> 2) << 6);
        km[j] = g_km[col];
        kv[j] = g_kv[col];
    }

#pragma unroll
    for (int i = 0; i < 8; i++) {
        const int row = n0 + tr * 4 + (i & 3) + ((i >> 2) << 6);
        float p[8], rowp = 0.f;
#pragma unroll
        for (int j = 0; j < 8; j++) {
            const float cov = acc[i][j] * INV255;
            const float num = (2.0f * qm[i] * km[j] + C1f) * (2.0f * cov + C2f);
            const float den =
                (qm[i] * qm[i] + km[j] * km[j] + C1f) * (qv[i] + kv[j] + C2f) + EPSf;
            p[j] = __expf(num / den);     // ssim bounded ~[-1,1]: exp safe w/o max
            rowp += p[j];
        }
        *(float4*)&g_S[(size_t)row * 1024 + m0 + tc * 4] =
            make_float4(p[0], p[1], p[2], p[3]);
        *(float4*)&g_S[(size_t)row * 1024 + m0 + 64 + tc * 4] =
            make_float4(p[4], p[5], p[6], p[7]);
        // reduce rowp over the 16 tc lanes (half-warp; lane = (tr&1)*16 + tc)
#pragma unroll
        for (int o = 8; o > 0; o >>= 1) rowp += __shfl_xor_sync(0xffffffffu, rowp, o);
        if (tc == 0) g_psum[blockIdx.x * NROWS + row] = rowp;   // deterministic partial
    }
}

// =================================================================================
// out = (P @ v) / rowsum :  [N,1024] x [1024,256] -> d_out.
// =================================================================================
__global__ __launch_bounds__(256, 2) void out_kernel(float* __restrict__ out) {
    extern __shared__ float sm[];
    float* Asm[2] = {sm, sm + A_BUF};
    float* Bsm[2] = {sm + 2 * A_BUF, sm + 2 * A_BUF + B_BUF};

    const int tid = threadIdx.x;
    const int n0 = blockIdx.y << 7;
    const int j0 = blockIdx.x << 7;
    const int tr = tid >> 4;
    const int tc = tid & 15;

    unsigned long long accp[8][4];
#pragma unroll
    for (int i = 0; i < 8; i++)
#pragma unroll
        for (int j = 0; j < 4; j++) accp[i][j] = 0ull;

    float4 av[4];
    lda_regs(av, &g_S[(size_t)n0 * 1024], 1024, tid);
    ldb_async(Bsm[0], &g_vmat[j0], 256, tid);
    sta_dup(av, Asm[0], tid);

#pragma unroll 1
    for (int t = 0; t < 32; t++) {
        cpa_wait_all();
        __syncthreads();
        if (t + 1 < 32) {
            ldb_async(Bsm[(t + 1) & 1], &g_vmat[(size_t)(t + 1) * 32 * 256 + j0], 256,
                      tid);
            lda_regs(av, &g_S[(size_t)n0 * 1024 + (t + 1) * 32], 1024, tid);
        }
        tile_mma(Asm[t & 1], Bsm[t & 1], tr, tc, accp);
        if (t + 1 < 32) sta_dup(av, Asm[(t + 1) & 1], tid);
    }

#pragma unroll
    for (int i = 0; i < 8; i++) {
        const int row = n0 + tr * 4 + (i & 3) + ((i >> 2) << 6);
        float s = 0.f;
#pragma unroll
        for (int b = 0; b < 8; b++) s += g_psum[b * NROWS + row];
        const float inv = 1.0f / s;
        float2 u0 = upk2(accp[i][0]);
        float2 u1 = upk2(accp[i][1]);
        float2 u2 = upk2(accp[i][2]);
        float2 u3 = upk2(accp[i][3]);
        *(float4*)&out[row * 256 + j0 + tc * 4] =
            make_float4(u0.x * inv, u0.y * inv, u1.x * inv, u1.y * inv);
        *(float4*)&out[row * 256 + j0 + 64 + tc * 4] =
            make_float4(u2.x * inv, u2.y * inv, u3.x * inv, u3.y * inv);
    }
}

// =================================================================================
extern "C" void kernel_launch(void* const* d_in, const int* in_sizes, int n_in,
                              void* d_out, int out_size) {
    (void)in_sizes; (void)n_in; (void)out_size;
    const float* x   = (const float*)d_in[0];   // [8192, 8, 256] -> [65536, 256]
    const float* mem = (const float*)d_in[1];   // [1024, 16, 16] -> [1024, 256]
    const float* Wq  = (const float*)d_in[2];   // [256, 256]
    const float* Wk  = (const float*)d_in[3];
    const float* Wv  = (const float*)d_in[4];
    float* out = (float*)d_out;

    cudaFuncSetAttribute(ssim_kernel, cudaFuncAttributeMaxDynamicSharedMemorySize,
                         SMEM_BYTES);
    cudaFuncSetAttribute(out_kernel, cudaFuncAttributeMaxDynamicSharedMemorySize,
                         SMEM_BYTES);

    rowgemm_kernel<1><<<16, 256>>>(mem, Wk);               // k -> centered kcT + km/kv
    rowgemm_kernel<2><<<16, 256>>>(mem, Wv);               // v
    rowgemm_kernel<0><<<1024, 256>>>(x, Wq);               // q raw + qm/qv
    ssim_kernel<<<dim3(8, 512), 256, SMEM_BYTES>>>();      // P = exp(ssim), psum
    out_kernel<<<dim3(2, 512), 256, SMEM_BYTES>>>(out);    // out = (P @ v)/rowsum
}

// round 9
// speedup vs baseline: 2.0855x; 2.0855x over previous
#include <cuda_runtime.h>

#define NROWS 65536   // N_TOKENS * BATCH
#define FDIM  256     // HW
#define MDIM  1024    // MEM_DIM

// ---------------- scratch (static device globals; no allocation) ----------------
__device__ float g_q[NROWS * FDIM];             // raw q, row-major [N, F]        (64 MB)
__device__ float g_qm[NROWS];
__device__ float g_qv[NROWS];
__device__ float g_kcT[FDIM * MDIM];            // centered k, TRANSPOSED [F, M]  (1 MB)
__device__ float g_vmat[MDIM * FDIM];           // v, row-major [M, F]            (1 MB)
__device__ float g_km[MDIM];
__device__ float g_kv[MDIM];
__device__ float g_S[(size_t)NROWS * MDIM];     // p = exp(ssim) [N, M]           (256 MB)
__device__ float g_psum[8 * NROWS];             // per-m-block partial row sums   (2 MB)

// ---------------- packed f32x2 helpers (full-rate FP32 on sm_103a) --------------
__device__ __forceinline__ unsigned long long pk2(float lo, float hi) {
    unsigned long long r;
    asm("mov.b64 %0, {%1, %2};" : "=l"(r) : "f"(lo), "f"(hi));
    return r;
}
__device__ __forceinline__ void fma2(unsigned long long& d, unsigned long long a,
                                     unsigned long long b) {
    asm("fma.rn.f32x2 %0, %1, %2, %0;" : "+l"(d) : "l"(a), "l"(b));
}
__device__ __forceinline__ float2 upk2(unsigned long long v) {
    float2 r;
    asm("mov.b64 {%0, %1}, %2;" : "=f"(r.x), "=f"(r.y) : "l"(v));
    return r;
}

// ---------------- cp.async helpers ----------------------------------------------
__device__ __forceinline__ void cpa16(void* dst, const void* src) {
    unsigned saddr = (unsigned)__cvta_generic_to_shared(dst);
    asm volatile("cp.async.cg.shared.global [%0], [%1], 16;" ::"r"(saddr), "l"(src));
}
__device__ __forceinline__ void cpa_commit() {
    asm volatile("cp.async.commit_group;" ::: "memory");
}
__device__ __forceinline__ void cpa_wait_all() {
    asm volatile("cp.async.wait_group 0;" ::: "memory");
}

// =================================================================================
// rowgemm: C[64 x 256] = A_tile @ W^T   (W is [256,256] row-major)
// MODE 0: q  -> row stats (mean/var), RAW rows to g_q, g_qm/g_qv
// MODE 1: k  -> row stats, centered TRANSPOSED to g_kcT, g_km/g_kv
// MODE 2: v  -> plain row-major store to g_vmat
// =================================================================================
template <int MODE>
__global__ __launch_bounds__(256, 2) void rowgemm_kernel(const float* __restrict__ A,
                                                         const float* __restrict__ W) {
    __shared__ float As[16][68];    // As[kk][row]
    __shared__ float Bs[16][260];   // Bs[kk][col]

    const int tid = threadIdx.x;
    const int n0  = blockIdx.x * 64;
    const int tr  = tid >> 5;   // 0..7
    const int tc  = tid & 31;   // 0..31

    unsigned long long accp[8][4];
#pragma unroll
    for (int i = 0; i < 8; i++)
#pragma unroll
        for (int j = 0; j < 4; j++) accp[i][j] = 0ull;

    for (int k0 = 0; k0 < 256; k0 += 16) {
        {   // A tile 64x16 (transpose into smem)
            int r = tid >> 2;
            int c = (tid & 3) << 2;
            float4 v = *(const float4*)&A[(n0 + r) * 256 + k0 + c];
            As[c + 0][r] = v.x; As[c + 1][r] = v.y; As[c + 2][r] = v.z; As[c + 3][r] = v.w;
        }
#pragma unroll
        for (int it = 0; it < 4; it++) {   // W tile 256x16 (transpose into smem)
            int fid = tid + (it << 8);
            int j = fid >> 2;
            int c = (fid & 3) << 2;
            float4 v = *(const float4*)&W[j * 256 + k0 + c];
            Bs[c + 0][j] = v.x; Bs[c + 1][j] = v.y; Bs[c + 2][j] = v.z; Bs[c + 3][j] = v.w;
        }
        __syncthreads();
#pragma unroll
        for (int kk = 0; kk < 16; kk++) {
            float4 a0 = *(const float4*)&As[kk][tr * 4];
            float4 a1 = *(const float4*)&As[kk][32 + tr * 4];
            ulonglong2 b0 = *(const ulonglong2*)(const void*)&Bs[kk][tc * 4];
            ulonglong2 b1 = *(const ulonglong2*)(const void*)&Bs[kk][128 + tc * 4];
            unsigned long long ap[8] = {pk2(a0.x, a0.x), pk2(a0.y, a0.y), pk2(a0.z, a0.z),
                                        pk2(a0.w, a0.w), pk2(a1.x, a1.x), pk2(a1.y, a1.y),
                                        pk2(a1.z, a1.z), pk2(a1.w, a1.w)};
            unsigned long long bv[4] = {b0.x, b0.y, b1.x, b1.y};
#pragma unroll
            for (int i = 0; i < 8; i++)
#pragma unroll
                for (int j = 0; j < 4; j++) fma2(accp[i][j], ap[i], bv[j]);
        }
        __syncthreads();
    }

    float acc[8][8];
#pragma unroll
    for (int i = 0; i < 8; i++)
#pragma unroll
        for (int j2 = 0; j2 < 4; j2++) {
            float2 u = upk2(accp[i][j2]);
            acc[i][2 * j2 + 0] = u.x;
            acc[i][2 * j2 + 1] = u.y;
        }

#pragma unroll
    for (int i = 0; i < 8; i++) {
        const int row = n0 + tr * 4 + (i & 3) + ((i >> 2) << 5);
        if (MODE == 2) {
            *(float4*)&g_vmat[row * 256 + tc * 4] =
                make_float4(acc[i][0], acc[i][1], acc[i][2], acc[i][3]);
            *(float4*)&g_vmat[row * 256 + 128 + tc * 4] =
                make_float4(acc[i][4], acc[i][5], acc[i][6], acc[i][7]);
        } else {
            float s = 0.f, ss = 0.f;
#pragma unroll
            for (int j = 0; j < 8; j++) { s += acc[i][j]; ss += acc[i][j] * acc[i][j]; }
#pragma unroll
            for (int o = 16; o > 0; o >>= 1) {
                s  += __shfl_xor_sync(0xffffffffu, s, o);
                ss += __shfl_xor_sync(0xffffffffu, ss, o);
            }
            const float mean = s * (1.0f / 256.0f);
            const float var  = (ss - 256.0f * mean * mean) * (1.0f / 255.0f);
            if (MODE == 0) {
                if (tc == 0) { g_qm[row] = mean; g_qv[row] = var; }
                // store RAW q: cov = q . kcT is exact since sum(kcT col) == 0
                *(float4*)&g_q[row * 256 + tc * 4] =
                    make_float4(acc[i][0], acc[i][1], acc[i][2], acc[i][3]);
                *(float4*)&g_q[row * 256 + 128 + tc * 4] =
                    make_float4(acc[i][4], acc[i][5], acc[i][6], acc[i][7]);
            } else {   // MODE 1: k -> centered transposed
                if (tc == 0) { g_km[row] = mean; g_kv[row] = var; }
#pragma unroll
                for (int j = 0; j < 8; j++) {
                    const int col = tc * 4 + (j & 3) + ((j >> 2) << 7);
                    g_kcT[col * 1024 + row] = acc[i][j] - mean;
                }
            }
        }
    }
}

// =================================================================================
// 128x128x(BK=32) tile engine — R5 smem layout (PROVEN: transposed A + pk2 inner
// loop), now double-buffered with ONE barrier per tile:
//   tile t:  LDG A(t+1)->regs + cp.async B(t+1)   (latency hidden under mma)
//            mma first half (kk 0..15) on buffers[t]
//            STS A(t+1) regs -> spare buffer      (regs die mid-mma: low pressure)
//            mma second half (kk 16..31)
//            cp.async wait; __syncthreads
// Thread (tr=tid>>4, tc=tid&15): rows tr*4+i (+64), cols tc*4+j (+64).
// =================================================================================
#define T_STR 132
#define T_BUF (32 * T_STR)            // 4224 floats per buffer
#define SMEM_BYTES (4 * T_BUF * 4)    // 2xA + 2xB = 67584 bytes

__device__ __forceinline__ void lda_regs(float4 av[4], const float* __restrict__ Agl,
                                         int a_ld, int tid) {
#pragma unroll
    for (int it = 0; it < 4; it++) {   // A tile: 128 rows x 32 floats, coalesced
        int ch = tid + (it << 8);
        int r = ch >> 3, c = (ch & 7) << 2;
        av[it] = *(const float4*)&Agl[(size_t)r * a_ld + c];
    }
}
__device__ __forceinline__ void sts_a(const float4 av[4], float* As, int tid) {
#pragma unroll
    for (int it = 0; it < 4; it++) {   // transpose into As[kk][row] (stride 132)
        int ch = tid + (it << 8);
        int r = ch >> 3, c = (ch & 7) << 2;
        As[(c + 0) * T_STR + r] = av[it].x;
        As[(c + 1) * T_STR + r] = av[it].y;
        As[(c + 2) * T_STR + r] = av[it].z;
        As[(c + 3) * T_STR + r] = av[it].w;
    }
}
__device__ __forceinline__ void ldb_async(float* Bs, const float* __restrict__ Bgl,
                                          int b_ld, int tid) {
#pragma unroll
    for (int it = 0; it < 4; it++) {   // B tile: 32 rows x 128 floats, verbatim
        int ch = tid + (it << 8);
        int rr = ch >> 5, cc = (ch & 31) << 2;
        cpa16(&Bs[rr * T_STR + cc], &Bgl[(size_t)rr * b_ld + cc]);
    }
    cpa_commit();
}

template <int K0, int K1>
__device__ __forceinline__ void mma_range(const float* __restrict__ As,
                                          const float* __restrict__ Bs, int tr, int tc,
                                          unsigned long long accp[8][4]) {
#pragma unroll
    for (int kk = K0; kk < K1; kk++) {
        float4 a0 = *(const float4*)&As[kk * T_STR + tr * 4];
        float4 a1 = *(const float4*)&As[kk * T_STR + 64 + tr * 4];
        ulonglong2 b0 = *(const ulonglong2*)(const void*)&Bs[kk * T_STR + tc * 4];
        ulonglong2 b1 = *(const ulonglong2*)(const void*)&Bs[kk * T_STR + 64 + tc * 4];
        unsigned long long ap[8] = {pk2(a0.x, a0.x), pk2(a0.y, a0.y), pk2(a0.z, a0.z),
                                    pk2(a0.w, a0.w), pk2(a1.x, a1.x), pk2(a1.y, a1.y),
                                    pk2(a1.z, a1.z), pk2(a1.w, a1.w)};
        unsigned long long bv[4] = {b0.x, b0.y, b1.x, b1.y};
#pragma unroll
        for (int i = 0; i < 8; i++)
#pragma unroll
            for (int j = 0; j < 4; j++) fma2(accp[i][j], ap[i], bv[j]);
    }
}

// =================================================================================
// ssim: P[N, M] = exp(ssim(q, k));  cov = q @ kcT / 255 (q raw: mean term vanishes)
// also writes deterministic per-m-block row-sum partials to g_psum.
// =================================================================================
__global__ __launch_bounds__(256, 2) void ssim_kernel() {
    extern __shared__ float sm[];
    float* Asm[2] = {sm, sm + T_BUF};
    float* Bsm[2] = {sm + 2 * T_BUF, sm + 3 * T_BUF};

    const int tid = threadIdx.x;
    const int n0 = blockIdx.y << 7;
    const int m0 = blockIdx.x << 7;
    const int tr = tid >> 4;
    const int tc = tid & 15;

    unsigned long long accp[8][4];
#pragma unroll
    for (int i = 0; i < 8; i++)
#pragma unroll
        for (int j = 0; j < 4; j++) accp[i][j] = 0ull;

    float4 av[4];
    lda_regs(av, &g_q[(size_t)n0 * 256], 256, tid);
    ldb_async(Bsm[0], &g_kcT[m0], 1024, tid);
    sts_a(av, Asm[0], tid);
    cpa_wait_all();
    __syncthreads();

#pragma unroll 1
    for (int t = 0; t < 8; t++) {
        const bool more = (t + 1 < 8);
        if (more) {
            ldb_async(Bsm[(t + 1) & 1], &g_kcT[(size_t)(t + 1) * 32 * 1024 + m0], 1024,
                      tid);
            lda_regs(av, &g_q[(size_t)n0 * 256 + (t + 1) * 32], 256, tid);
        }
        mma_range<0, 16>(Asm[t & 1], Bsm[t & 1], tr, tc, accp);
        if (more) sts_a(av, Asm[(t + 1) & 1], tid);
        mma_range<16, 32>(Asm[t & 1], Bsm[t & 1], tr, tc, accp);
        if (more) cpa_wait_all();
        __syncthreads();
    }

    float acc[8][8];
#pragma unroll
    for (int i = 0; i < 8; i++)
#pragma unroll
        for (int j2 = 0; j2 < 4; j2++) {
            float2 u = upk2(accp[i][j2]);
            acc[i][2 * j2 + 0] = u.x;
            acc[i][2 * j2 + 1] = u.y;
        }

    const float C1f = 0.01f, C2f = 0.03f, EPSf = 1e-8f, INV255 = 1.0f / 255.0f;

    float qm[8], qv[8], km[8], kv[8];
#pragma unroll
    for (int i = 0; i < 8; i++) {
        const int row = n0 + tr * 4 + (i & 3) + ((i >> 2) << 6);
        qm[i] = g_qm[row];
        qv[i] = g_qv[row];
    }
#pragma unroll
    for (int j = 0; j < 8; j++) {
        const int col = m0 + tc * 4 + (j & 3) + ((j >> 2) << 6);
        km[j] = g_km[col];
        kv[j] = g_kv[col];
    }

#pragma unroll
    for (int i = 0; i < 8; i++) {
        const int row = n0 + tr * 4 + (i & 3) + ((i >> 2) << 6);
        float p[8], rowp = 0.f;
#pragma unroll
        for (int j = 0; j < 8; j++) {
            const float cov = acc[i][j] * INV255;
            const float num = (2.0f * qm[i] * km[j] + C1f) * (2.0f * cov + C2f);
            const float den =
                (qm[i] * qm[i] + km[j] * km[j] + C1f) * (qv[i] + kv[j] + C2f) + EPSf;
            p[j] = __expf(num / den);     // ssim bounded ~[-1,1]: exp safe w/o max
            rowp += p[j];
        }
        *(float4*)&g_S[(size_t)row * 1024 + m0 + tc * 4] =
            make_float4(p[0], p[1], p[2], p[3]);
        *(float4*)&g_S[(size_t)row * 1024 + m0 + 64 + tc * 4] =
            make_float4(p[4], p[5], p[6], p[7]);
        // reduce rowp over the 16 tc lanes (half-warp; lane = (tr&1)*16 + tc)
#pragma unroll
        for (int o = 8; o > 0; o >>= 1) rowp += __shfl_xor_sync(0xffffffffu, rowp, o);
        if (tc == 0) g_psum[blockIdx.x * NROWS + row] = rowp;   // deterministic partial
    }
}

// =================================================================================
// out = (P @ v) / rowsum :  [N,1024] x [1024,256] -> d_out.
// =================================================================================
__global__ __launch_bounds__(256, 2) void out_kernel(float* __restrict__ out) {
    extern __shared__ float sm[];
    float* Asm[2] = {sm, sm + T_BUF};
    float* Bsm[2] = {sm + 2 * T_BUF, sm + 3 * T_BUF};

    const int tid = threadIdx.x;
    const int n0 = blockIdx.y << 7;
    const int j0 = blockIdx.x << 7;
    const int tr = tid >> 4;
    const int tc = tid & 15;

    unsigned long long accp[8][4];
#pragma unroll
    for (int i = 0; i < 8; i++)
#pragma unroll
        for (int j = 0; j < 4; j++) accp[i][j] = 0ull;

    float4 av[4];
    lda_regs(av, &g_S[(size_t)n0 * 1024], 1024, tid);
    ldb_async(Bsm[0], &g_vmat[j0], 256, tid);
    sts_a(av, Asm[0], tid);
    cpa_wait_all();
    __syncthreads();

#pragma unroll 1
    for (int t = 0; t < 32; t++) {
        const bool more = (t + 1 < 32);
        if (more) {
            ldb_async(Bsm[(t + 1) & 1], &g_vmat[(size_t)(t + 1) * 32 * 256 + j0], 256,
                      tid);
            lda_regs(av, &g_S[(size_t)n0 * 1024 + (t + 1) * 32], 1024, tid);
        }
        mma_range<0, 16>(Asm[t & 1], Bsm[t & 1], tr, tc, accp);
        if (more) sts_a(av, Asm[(t + 1) & 1], tid);
        mma_range<16, 32>(Asm[t & 1], Bsm[t & 1], tr, tc, accp);
        if (more) cpa_wait_all();
        __syncthreads();
    }

#pragma unroll
    for (int i = 0; i < 8; i++) {
        const int row = n0 + tr * 4 + (i & 3) + ((i >> 2) << 6);
        float s = 0.f;
#pragma unroll
        for (int b = 0; b < 8; b++) s += g_psum[b * NROWS + row];
        const float inv = 1.0f / s;
        float2 u0 = upk2(accp[i][0]);
        float2 u1 = upk2(accp[i][1]);
        float2 u2 = upk2(accp[i][2]);
        float2 u3 = upk2(accp[i][3]);
        *(float4*)&out[row * 256 + j0 + tc * 4] =
            make_float4(u0.x * inv, u0.y * inv, u1.x * inv, u1.y * inv);
        *(float4*)&out[row * 256 + j0 + 64 + tc * 4] =
            make_float4(u2.x * inv, u2.y * inv, u3.x * inv, u3.y * inv);
    }
}

// =================================================================================
extern "C" void kernel_launch(void* const* d_in, const int* in_sizes, int n_in,
                              void* d_out, int out_size) {
    (void)in_sizes; (void)n_in; (void)out_size;
    const float* x   = (const float*)d_in[0];   // [8192, 8, 256] -> [65536, 256]
    const float* mem = (const float*)d_in[1];   // [1024, 16, 16] -> [1024, 256]
    const float* Wq  = (const float*)d_in[2];   // [256, 256]
    const float* Wk  = (const float*)d_in[3];
    const float* Wv  = (const float*)d_in[4];
    float* out = (float*)d_out;

    cudaFuncSetAttribute(ssim_kernel, cudaFuncAttributeMaxDynamicSharedMemorySize,
                         SMEM_BYTES);
    cudaFuncSetAttribute(out_kernel, cudaFuncAttributeMaxDynamicSharedMemorySize,
                         SMEM_BYTES);

    rowgemm_kernel<1><<<16, 256>>>(mem, Wk);               // k -> centered kcT + km/kv
    rowgemm_kernel<2><<<16, 256>>>(mem, Wv);               // v
    rowgemm_kernel<0><<<1024, 256>>>(x, Wq);               // q raw + qm/qv
    ssim_kernel<<<dim3(8, 512), 256, SMEM_BYTES>>>();      // P = exp(ssim), psum
    out_kernel<<<dim3(2, 512), 256, SMEM_BYTES>>>(out);    // out = (P @ v)/rowsum
}

// round 11
// speedup vs baseline: 2.2351x; 1.0717x over previous
#include <cuda_runtime.h>

#define NROWS 65536   // N_TOKENS * BATCH
#define FDIM  256     // HW
#define MDIM  1024    // MEM_DIM

// ---------------- scratch (static device globals; no allocation) ----------------
__device__ float g_qT[FDIM * NROWS];            // q TRANSPOSED [F, N]            (64 MB)
__device__ float g_qm[NROWS];
__device__ float g_qv[NROWS];
__device__ float g_kcT[FDIM * MDIM];            // centered k, TRANSPOSED [F, M]  (1 MB)
__device__ float g_vmat[MDIM * FDIM];           // v, row-major [M, F]            (1 MB)
__device__ float g_km[MDIM];
__device__ float g_kv[MDIM];
__device__ float g_ST[(size_t)MDIM * NROWS];    // p = exp(ssim) TRANSPOSED [M,N] (256 MB)
__device__ float g_psum[8 * NROWS];             // per-m-block partial col sums   (2 MB)

// ---------------- packed f32x2 helpers (full-rate FP32 on sm_103a) --------------
__device__ __forceinline__ unsigned long long pk2(float lo, float hi) {
    unsigned long long r;
    asm("mov.b64 %0, {%1, %2};" : "=l"(r) : "f"(lo), "f"(hi));
    return r;
}
__device__ __forceinline__ void fma2(unsigned long long& d, unsigned long long a,
                                     unsigned long long b) {
    asm("fma.rn.f32x2 %0, %1, %2, %0;" : "+l"(d) : "l"(a), "l"(b));
}
__device__ __forceinline__ float2 upk2(unsigned long long v) {
    float2 r;
    asm("mov.b64 {%0, %1}, %2;" : "=f"(r.x), "=f"(r.y) : "l"(v));
    return r;
}

// ---------------- cp.async helpers ----------------------------------------------
__device__ __forceinline__ void cpa16(void* dst, const void* src) {
    unsigned saddr = (unsigned)__cvta_generic_to_shared(dst);
    asm volatile("cp.async.cg.shared.global [%0], [%1], 16;" ::"r"(saddr), "l"(src));
}
__device__ __forceinline__ void cpa_commit() {
    asm volatile("cp.async.commit_group;" ::: "memory");
}
__device__ __forceinline__ void cpa_wait_all() {
    asm volatile("cp.async.wait_group 0;" ::: "memory");
}

// =================================================================================
// rowgemm: C[64 x 256] = A_tile @ W^T   (W is [256,256] row-major)
// MODE 0: q  -> row stats, TRANSPOSED raw q to g_qT (smem transpose), g_qm/g_qv
// MODE 1: k  -> row stats, centered TRANSPOSED to g_kcT, g_km/g_kv
// MODE 2: v  -> plain row-major store to g_vmat
// =================================================================================
#define TS_STR 65   // transpose buffer stride (writes 4-way conflict, reads clean)

template <int MODE>
__global__ __launch_bounds__(256, 2) void rowgemm_kernel(const float* __restrict__ A,
                                                         const float* __restrict__ W) {
    __shared__ float As[16][68];    // As[kk][row]
    __shared__ float Bs[16][260];   // Bs[kk][col]
    extern __shared__ float Ts[];   // MODE 0 only: [256][TS_STR] transpose buffer

    const int tid = threadIdx.x;
    const int n0  = blockIdx.x * 64;
    const int tr  = tid >> 5;   // 0..7
    const int tc  = tid & 31;   // 0..31

    unsigned long long accp[8][4];
#pragma unroll
    for (int i = 0; i < 8; i++)
#pragma unroll
        for (int j = 0; j < 4; j++) accp[i][j] = 0ull;

    for (int k0 = 0; k0 < 256; k0 += 16) {
        {   // A tile 64x16 (transpose into smem)
            int r = tid >> 2;
            int c = (tid & 3) << 2;
            float4 v = *(const float4*)&A[(n0 + r) * 256 + k0 + c];
            As[c + 0][r] = v.x; As[c + 1][r] = v.y; As[c + 2][r] = v.z; As[c + 3][r] = v.w;
        }
#pragma unroll
        for (int it = 0; it < 4; it++) {   // W tile 256x16 (transpose into smem)
            int fid = tid + (it << 8);
            int j = fid >> 2;
            int c = (fid & 3) << 2;
            float4 v = *(const float4*)&W[j * 256 + k0 + c];
            Bs[c + 0][j] = v.x; Bs[c + 1][j] = v.y; Bs[c + 2][j] = v.z; Bs[c + 3][j] = v.w;
        }
        __syncthreads();
#pragma unroll
        for (int kk = 0; kk < 16; kk++) {
            float4 a0 = *(const float4*)&As[kk][tr * 4];
            float4 a1 = *(const float4*)&As[kk][32 + tr * 4];
            ulonglong2 b0 = *(const ulonglong2*)(const void*)&Bs[kk][tc * 4];
            ulonglong2 b1 = *(const ulonglong2*)(const void*)&Bs[kk][128 + tc * 4];
            unsigned long long ap[8] = {pk2(a0.x, a0.x), pk2(a0.y, a0.y), pk2(a0.z, a0.z),
                                        pk2(a0.w, a0.w), pk2(a1.x, a1.x), pk2(a1.y, a1.y),
                                        pk2(a1.z, a1.z), pk2(a1.w, a1.w)};
            unsigned long long bv[4] = {b0.x, b0.y, b1.x, b1.y};
#pragma unroll
            for (int i = 0; i < 8; i++)
#pragma unroll
                for (int j = 0; j < 4; j++) fma2(accp[i][j], ap[i], bv[j]);
        }
        __syncthreads();
    }

    float acc[8][8];
#pragma unroll
    for (int i = 0; i < 8; i++)
#pragma unroll
        for (int j2 = 0; j2 < 4; j2++) {
            float2 u = upk2(accp[i][j2]);
            acc[i][2 * j2 + 0] = u.x;
            acc[i][2 * j2 + 1] = u.y;
        }

#pragma unroll
    for (int i = 0; i < 8; i++) {
        const int rloc = tr * 4 + (i & 3) + ((i >> 2) << 5);   // 0..63
        const int row  = n0 + rloc;
        if (MODE == 2) {
            *(float4*)&g_vmat[row * 256 + tc * 4] =
                make_float4(acc[i][0], acc[i][1], acc[i][2], acc[i][3]);
            *(float4*)&g_vmat[row * 256 + 128 + tc * 4] =
                make_float4(acc[i][4], acc[i][5], acc[i][6], acc[i][7]);
        } else {
            float s = 0.f, ss = 0.f;
#pragma unroll
            for (int j = 0; j < 8; j++) { s += acc[i][j]; ss += acc[i][j] * acc[i][j]; }
#pragma unroll
            for (int o = 16; o > 0; o >>= 1) {
                s  += __shfl_xor_sync(0xffffffffu, s, o);
                ss += __shfl_xor_sync(0xffffffffu, ss, o);
            }
            const float mean = s * (1.0f / 256.0f);
            const float var  = (ss - 256.0f * mean * mean) * (1.0f / 255.0f);
            if (MODE == 0) {
                if (tc == 0) { g_qm[row] = mean; g_qv[row] = var; }
                // RAW q into transpose buffer (cov = q . kc exact: sum(kc)==0)
#pragma unroll
                for (int j = 0; j < 8; j++) {
                    const int f = tc * 4 + (j & 3) + ((j >> 2) << 7);
                    Ts[f * TS_STR + rloc] = acc[i][j];
                }
            } else {   // MODE 1: k -> centered transposed
                if (tc == 0) { g_km[row] = mean; g_kv[row] = var; }
#pragma unroll
                for (int j = 0; j < 8; j++) {
                    const int col = tc * 4 + (j & 3) + ((j >> 2) << 7);
                    g_kcT[col * 1024 + row] = acc[i][j] - mean;
                }
            }
        }
    }

    if (MODE == 0) {   // coalesced transposed write: thread tid owns feature f=tid
        __syncthreads();
        const float* src = &Ts[tid * TS_STR];
        float* dst = &g_qT[(size_t)tid * NROWS + n0];
#pragma unroll
        for (int r = 0; r < 64; r += 4)
            *(float4*)&dst[r] = make_float4(src[r], src[r + 1], src[r + 2], src[r + 3]);
    }
}

// =================================================================================
// 128x128x(BK=32) tile engine — both operands verbatim K-major via cp.async.
// Double-buffered, ONE barrier per tile, no register staging (regs ~100).
// Thread (tr=tid>>4, tc=tid&15): A-rows tr*4+i (+64), B-cols tc*4+j (+64).
// =================================================================================
#define T_STR 132
#define T_BUF (32 * T_STR)            // 4224 floats per buffer
#define SMEM_BYTES (4 * T_BUF * 4)    // 2xA + 2xB = 67584 bytes

__device__ __forceinline__ void ld_tile(float* dst, const float* __restrict__ src,
                                        size_t row_stride, int tid) {
#pragma unroll
    for (int it = 0; it < 4; it++) {   // 32 rows x 128 floats, verbatim
        int ch = tid + (it << 8);
        int rr = ch >> 5, cc = (ch & 31) << 2;
        cpa16(&dst[rr * T_STR + cc], &src[(size_t)rr * row_stride + cc]);
    }
}

__device__ __forceinline__ void tile_mma(const float* __restrict__ As,
                                         const float* __restrict__ Bs, int tr, int tc,
                                         unsigned long long accp[8][4]) {
#pragma unroll
    for (int kk = 0; kk < 32; kk++) {
        float4 a0 = *(const float4*)&As[kk * T_STR + tr * 4];
        float4 a1 = *(const float4*)&As[kk * T_STR + 64 + tr * 4];
        ulonglong2 b0 = *(const ulonglong2*)(const void*)&Bs[kk * T_STR + tc * 4];
        ulonglong2 b1 = *(const ulonglong2*)(const void*)&Bs[kk * T_STR + 64 + tc * 4];
        unsigned long long ap[8] = {pk2(a0.x, a0.x), pk2(a0.y, a0.y), pk2(a0.z, a0.z),
                                    pk2(a0.w, a0.w), pk2(a1.x, a1.x), pk2(a1.y, a1.y),
                                    pk2(a1.z, a1.z), pk2(a1.w, a1.w)};
        unsigned long long bv[4] = {b0.x, b0.y, b1.x, b1.y};
#pragma unroll
        for (int i = 0; i < 8; i++)
#pragma unroll
            for (int j = 0; j < 4; j++) fma2(accp[i][j], ap[i], bv[j]);
    }
}

// =================================================================================
// ssimT: ST[m, n] = exp(ssim);  A = g_kcT (K-major, verbatim), B = g_qT (verbatim).
// cov = kc . q / 255 (raw q: mean term vanishes). Writes per-m-block column sums.
// =================================================================================
__global__ __launch_bounds__(256, 2) void ssim_kernel() {
    extern __shared__ float sm[];
    float* Asm[2] = {sm, sm + T_BUF};
    float* Bsm[2] = {sm + 2 * T_BUF, sm + 3 * T_BUF};

    const int tid = threadIdx.x;
    const int n0 = blockIdx.x << 7;
    const int m0 = blockIdx.y << 7;
    const int tr = tid >> 4;
    const int tc = tid & 15;

    unsigned long long accp[8][4];
#pragma unroll
    for (int i = 0; i < 8; i++)
#pragma unroll
        for (int j = 0; j < 4; j++) accp[i][j] = 0ull;

    ld_tile(Asm[0], &g_kcT[m0], 1024, tid);
    ld_tile(Bsm[0], &g_qT[n0], NROWS, tid);
    cpa_commit();
    cpa_wait_all();
    __syncthreads();

#pragma unroll 1
    for (int t = 0; t < 8; t++) {
        const bool more = (t + 1 < 8);
        if (more) {
            ld_tile(Asm[(t + 1) & 1], &g_kcT[(t + 1) * 32 * 1024 + m0], 1024, tid);
            ld_tile(Bsm[(t + 1) & 1], &g_qT[(size_t)(t + 1) * 32 * NROWS + n0], NROWS,
                    tid);
            cpa_commit();
        }
        tile_mma(Asm[t & 1], Bsm[t & 1], tr, tc, accp);
        if (more) cpa_wait_all();
        __syncthreads();
    }

    float acc[8][8];
#pragma unroll
    for (int i = 0; i < 8; i++)
#pragma unroll
        for (int j2 = 0; j2 < 4; j2++) {
            float2 u = upk2(accp[i][j2]);
            acc[i][2 * j2 + 0] = u.x;
            acc[i][2 * j2 + 1] = u.y;
        }

    const float C1f = 0.01f, C2f = 0.03f, EPSf = 1e-8f, INV255 = 1.0f / 255.0f;

    float km[8], kv[8], qm[8], qv[8];
#pragma unroll
    for (int i = 0; i < 8; i++) {   // A side = m
        const int mrow = m0 + tr * 4 + (i & 3) + ((i >> 2) << 6);
        km[i] = g_km[mrow];
        kv[i] = g_kv[mrow];
    }
#pragma unroll
    for (int j = 0; j < 8; j++) {   // B side = n
        const int ncol = n0 + tc * 4 + (j & 3) + ((j >> 2) << 6);
        qm[j] = g_qm[ncol];
        qv[j] = g_qv[ncol];
    }

    float colp[8];
#pragma unroll
    for (int j = 0; j < 8; j++) colp[j] = 0.f;

#pragma unroll
    for (int i = 0; i < 8; i++) {
        const int mrow = m0 + tr * 4 + (i & 3) + ((i >> 2) << 6);
        float p[8];
#pragma unroll
        for (int j = 0; j < 8; j++) {
            const float cov = acc[i][j] * INV255;
            const float num = (2.0f * qm[j] * km[i] + C1f) * (2.0f * cov + C2f);
            const float den =
                (qm[j] * qm[j] + km[i] * km[i] + C1f) * (qv[j] + kv[i] + C2f) + EPSf;
            p[j] = __expf(num / den);     // ssim bounded ~[-1,1]: exp safe w/o max
            colp[j] += p[j];
        }
        *(float4*)&g_ST[(size_t)mrow * NROWS + n0 + tc * 4] =
            make_float4(p[0], p[1], p[2], p[3]);
        *(float4*)&g_ST[(size_t)mrow * NROWS + n0 + 64 + tc * 4] =
            make_float4(p[4], p[5], p[6], p[7]);
    }

    // column-sum over the 128 m's of this block: pair-reduce tr (xor16), then smem
#pragma unroll
    for (int j = 0; j < 8; j++)
        colp[j] += __shfl_xor_sync(0xffffffffu, colp[j], 16);
    float* red = sm;                       // reuse tile smem: red[8][128]
    const int warp = tid >> 5, lane = tid & 31;
    if (lane < 16) {
#pragma unroll
        for (int j = 0; j < 8; j++)
            red[warp * 128 + tc * 4 + (j & 3) + ((j >> 2) << 6)] = colp[j];
    }
    __syncthreads();
    if (tid < 128) {
        float s = 0.f;
#pragma unroll
        for (int w = 0; w < 8; w++) s += red[w * 128 + tid];
        g_psum[blockIdx.y * NROWS + n0 + tid] = s;    // unique writer: deterministic
    }
}

// =================================================================================
// out = (P @ v) / rowsum :  A = g_ST (K=m-major, verbatim), B = g_vmat.
// =================================================================================
__global__ __launch_bounds__(256, 2) void out_kernel(float* __restrict__ out) {
    extern __shared__ float sm[];
    float* Asm[2] = {sm, sm + T_BUF};
    float* Bsm[2] = {sm + 2 * T_BUF, sm + 3 * T_BUF};

    const int tid = threadIdx.x;
    const int n0 = blockIdx.y << 7;
    const int j0 = blockIdx.x << 7;
    const int tr = tid >> 4;
    const int tc = tid & 15;

    unsigned long long accp[8][4];
#pragma unroll
    for (int i = 0; i < 8; i++)
#pragma unroll
        for (int j = 0; j < 4; j++) accp[i][j] = 0ull;

    ld_tile(Asm[0], &g_ST[n0], NROWS, tid);
    ld_tile(Bsm[0], &g_vmat[j0], 256, tid);
    cpa_commit();
    cpa_wait_all();
    __syncthreads();

#pragma unroll 1
    for (int t = 0; t < 32; t++) {
        const bool more = (t + 1 < 32);
        if (more) {
            ld_tile(Asm[(t + 1) & 1], &g_ST[(size_t)(t + 1) * 32 * NROWS + n0], NROWS,
                    tid);
            ld_tile(Bsm[(t + 1) & 1], &g_vmat[(t + 1) * 32 * 256 + j0], 256, tid);
            cpa_commit();
        }
        tile_mma(Asm[t & 1], Bsm[t & 1], tr, tc, accp);
        if (more) cpa_wait_all();
        __syncthreads();
    }

#pragma unroll
    for (int i = 0; i < 8; i++) {
        const int row = n0 + tr * 4 + (i & 3) + ((i >> 2) << 6);
        float s = 0.f;
#pragma unroll
        for (int b = 0; b < 8; b++) s += g_psum[b * NROWS + row];
        const float inv = 1.0f / s;
        float2 u0 = upk2(accp[i][0]);
        float2 u1 = upk2(accp[i][1]);
        float2 u2 = upk2(accp[i][2]);
        float2 u3 = upk2(accp[i][3]);
        *(float4*)&out[row * 256 + j0 + tc * 4] =
            make_float4(u0.x * inv, u0.y * inv, u1.x * inv, u1.y * inv);
        *(float4*)&out[row * 256 + j0 + 64 + tc * 4] =
            make_float4(u2.x * inv, u2.y * inv, u3.x * inv, u3.y * inv);
    }
}

// =================================================================================
extern "C" void kernel_launch(void* const* d_in, const int* in_sizes, int n_in,
                              void* d_out, int out_size) {
    (void)in_sizes; (void)n_in; (void)out_size;
    const float* x   = (const float*)d_in[0];   // [8192, 8, 256] -> [65536, 256]
    const float* mem = (const float*)d_in[1];   // [1024, 16, 16] -> [1024, 256]
    const float* Wq  = (const float*)d_in[2];   // [256, 256]
    const float* Wk  = (const float*)d_in[3];
    const float* Wv  = (const float*)d_in[4];
    float* out = (float*)d_out;

    const int TS_BYTES = 256 * TS_STR * 4;      // 66560
    cudaFuncSetAttribute(rowgemm_kernel<0>, cudaFuncAttributeMaxDynamicSharedMemorySize,
                         TS_BYTES);
    cudaFuncSetAttribute(ssim_kernel, cudaFuncAttributeMaxDynamicSharedMemorySize,
                         SMEM_BYTES);
    cudaFuncSetAttribute(out_kernel, cudaFuncAttributeMaxDynamicSharedMemorySize,
                         SMEM_BYTES);

    rowgemm_kernel<1><<<16, 256>>>(mem, Wk);               // k -> centered kcT + km/kv
    rowgemm_kernel<2><<<16, 256>>>(mem, Wv);               // v
    rowgemm_kernel<0><<<1024, 256, TS_BYTES>>>(x, Wq);     // q -> qT + qm/qv
    ssim_kernel<<<dim3(512, 8), 256, SMEM_BYTES>>>();      // ST = exp(ssim), psum
    out_kernel<<<dim3(2, 512), 256, SMEM_BYTES>>>(out);    // out = (P @ v)/rowsum
}